// round 1
// baseline (speedup 1.0000x reference)
#include <cuda_runtime.h>
#include <cstdint>
#include <cstddef>

#define HH   32
#define SQ   2048
#define SKK  2048
#define DHH  128
#define BM   64
#define BN   64
#define LOG2E 1.4426950408889634f

// shared layout (float2 units):
//   sV[32][VSTR] : interleaved V pairs  sV[kt*4+c][n] = (V[kt*8+c][n], V[kt*8+c+4][n])
//   sL[64][LSTR] : interleaved L pairs  sL[r][kt*4+c] = (L[r][kt*8+c], L[r][kt*8+c+4])
#define VSTR 132
#define LSTR 36
#define SMEM_BYTES ((32 * VSTR + 64 * LSTR) * (int)sizeof(float2))

__device__ __forceinline__ uint32_t f2tf32(float f) {
    uint32_t u;
    asm("cvt.rna.tf32.f32 %0, %1;" : "=r"(u) : "f"(f));
    return u;
}
__device__ __forceinline__ float ex2f(float x) {
    float y;
    asm("ex2.approx.ftz.f32 %0, %1;" : "=f"(y) : "f"(x));
    return y;
}

__global__ __launch_bounds__(128)
void attn_sink_kernel(const float* __restrict__ logits,
                      const float* __restrict__ value,
                      const float* __restrict__ sinks,
                      float* __restrict__ out)
{
    extern __shared__ float2 smem[];
    float2* sV = smem;               // 32*VSTR float2
    float2* sL = smem + 32 * VSTR;   // 64*LSTR float2

    const int qt   = blockIdx.x;     // 0..31  (q tile)
    const int h    = blockIdx.y;     // 0..31  (head)
    const int tid  = threadIdx.x;
    const int lane = tid & 31;
    const int w    = tid >> 5;       // warp 0..3, owns rows [w*16, w*16+16)
    const int lc   = lane & 3;       // col-in-group
    const int lr   = lane >> 2;      // row-in-group

    const float* Lg = logits + ((size_t)h * SQ + (size_t)qt * BM) * SKK;
    const float* Vg = value  + (size_t)h * SKK * DHH;

    // accumulators: 16 n-tiles of m16n8 (c0,c1 -> row r0; c2,c3 -> row r0+8)
    float acc[16][4];
#pragma unroll
    for (int i = 0; i < 16; ++i) {
        acc[i][0] = 0.f; acc[i][1] = 0.f; acc[i][2] = 0.f; acc[i][3] = 0.f;
    }

    float m0 = -INFINITY, m1 = -INFINITY;   // running max, rows r0 / r0+8
    float l0 = 0.f,        l1 = 0.f;        // running denom

    const int r0 = w * 16 + lr;

    for (int kt = 0; kt < SKK / BN; ++kt) {
        __syncthreads();   // previous tile's LDS done before overwrite

        // ---- stage V tile [64 x 128] as interleaved tf32 pairs ----
        {
            const float* Vt = Vg + (size_t)kt * BN * DHH;
#pragma unroll
            for (int it = 0; it < 16; ++it) {
                int e  = it * 128 + tid;          // 0..2047
                int kp = e >> 6;                  // 0..31
                int n  = (e & 63) << 1;           // even 0..126
                int klo = ((kp >> 2) << 3) + (kp & 3);
                float2 g0 = *(const float2*)(Vt + (size_t)klo * DHH + n);
                float2 g1 = *(const float2*)(Vt + (size_t)(klo + 4) * DHH + n);
                uint32_t q[4] = { f2tf32(g0.x), f2tf32(g1.x), f2tf32(g0.y), f2tf32(g1.y) };
                *(float4*)(&sV[kp * VSTR + n]) = *(float4*)q;
            }
            // ---- stage L tile [64 x 64] fp32 as interleaved pairs ----
            const float* Lt = Lg + (size_t)kt * BN;
#pragma unroll
            for (int it = 0; it < 8; ++it) {
                int e = it * 128 + tid;           // 0..1023
                int r = e >> 4;                   // 0..63
                int j = e & 15;
                int ktile = j >> 1;
                int c = (j & 1) << 1;             // 0 or 2
                int col0 = ktile * 8 + c;
                float2 x0 = *(const float2*)(Lt + (size_t)r * SKK + col0);
                float2 x1 = *(const float2*)(Lt + (size_t)r * SKK + col0 + 4);
                float4 st = make_float4(x0.x, x1.x, x0.y, x1.y);
                *(float4*)(&sL[r * LSTR + ktile * 4 + c]) = st;
            }
        }
        __syncthreads();

        // ---- load A fragments (raw logits) for all 8 k-subtiles ----
        float2 A02[8], A13[8];
#pragma unroll
        for (int k = 0; k < 8; ++k) {
            A02[k] = sL[r0 * LSTR + k * 4 + lc];
            A13[k] = sL[(r0 + 8) * LSTR + k * 4 + lc];
        }

        // ---- tile max ----
        float tm0 = -INFINITY, tm1 = -INFINITY;
#pragma unroll
        for (int k = 0; k < 8; ++k) {
            tm0 = fmaxf(tm0, fmaxf(A02[k].x, A02[k].y));
            tm1 = fmaxf(tm1, fmaxf(A13[k].x, A13[k].y));
        }
        tm0 = fmaxf(tm0, __shfl_xor_sync(0xffffffffu, tm0, 1));
        tm0 = fmaxf(tm0, __shfl_xor_sync(0xffffffffu, tm0, 2));
        tm1 = fmaxf(tm1, __shfl_xor_sync(0xffffffffu, tm1, 1));
        tm1 = fmaxf(tm1, __shfl_xor_sync(0xffffffffu, tm1, 2));

        float nm0 = fmaxf(m0, tm0), nm1 = fmaxf(m1, tm1);
        float s0 = ex2f((m0 - nm0) * LOG2E);   // exp2(-inf)=0 on first tile
        float s1 = ex2f((m1 - nm1) * LOG2E);
        m0 = nm0; m1 = nm1;

        // ---- probs (exp), partial sums, convert to tf32 ----
        float ps0 = 0.f, ps1 = 0.f;
        uint32_t PA[8][4];
#pragma unroll
        for (int k = 0; k < 8; ++k) {
            float p0 = ex2f((A02[k].x - m0) * LOG2E);
            float p2 = ex2f((A02[k].y - m0) * LOG2E);
            float p1 = ex2f((A13[k].x - m1) * LOG2E);
            float p3 = ex2f((A13[k].y - m1) * LOG2E);
            ps0 += p0 + p2;
            ps1 += p1 + p3;
            PA[k][0] = f2tf32(p0);   // a0: row r0,   col lc
            PA[k][1] = f2tf32(p1);   // a1: row r0+8, col lc
            PA[k][2] = f2tf32(p2);   // a2: row r0,   col lc+4
            PA[k][3] = f2tf32(p3);   // a3: row r0+8, col lc+4
        }
        ps0 += __shfl_xor_sync(0xffffffffu, ps0, 1);
        ps0 += __shfl_xor_sync(0xffffffffu, ps0, 2);
        ps1 += __shfl_xor_sync(0xffffffffu, ps1, 1);
        ps1 += __shfl_xor_sync(0xffffffffu, ps1, 2);

        l0 = l0 * s0 + ps0;
        l1 = l1 * s1 + ps1;

        // ---- rescale accumulators ----
#pragma unroll
        for (int nt = 0; nt < 16; ++nt) {
            acc[nt][0] *= s0; acc[nt][1] *= s0;
            acc[nt][2] *= s1; acc[nt][3] *= s1;
        }

        // ---- P @ V via mma.sync tf32 ----
#pragma unroll
        for (int nt = 0; nt < 16; ++nt) {
#pragma unroll
            for (int k = 0; k < 8; ++k) {
                float2 b = sV[(k * 4 + lc) * VSTR + nt * 8 + lr];
                uint32_t b0 = __float_as_uint(b.x);
                uint32_t b1 = __float_as_uint(b.y);
                asm volatile(
                    "mma.sync.aligned.m16n8k8.row.col.f32.tf32.tf32.f32 "
                    "{%0,%1,%2,%3}, {%4,%5,%6,%7}, {%8,%9}, {%0,%1,%2,%3};\n"
                    : "+f"(acc[nt][0]), "+f"(acc[nt][1]),
                      "+f"(acc[nt][2]), "+f"(acc[nt][3])
                    : "r"(PA[k][0]), "r"(PA[k][1]), "r"(PA[k][2]), "r"(PA[k][3]),
                      "r"(b0), "r"(b1));
            }
        }
    }

    // ---- fold the sink into the denominator (its column is dropped from P@V) ----
    float snk = sinks[h];
    l0 += ex2f((snk - m0) * LOG2E);
    l1 += ex2f((snk - m1) * LOG2E);
    float inv0 = 1.0f / l0;
    float inv1 = 1.0f / l1;

    float* O = out + ((size_t)h * SQ + (size_t)qt * BM + r0) * DHH + lc * 2;
#pragma unroll
    for (int nt = 0; nt < 16; ++nt) {
        float2 o0 = make_float2(acc[nt][0] * inv0, acc[nt][1] * inv0);
        float2 o1 = make_float2(acc[nt][2] * inv1, acc[nt][3] * inv1);
        *(float2*)(O + nt * 8) = o0;
        *(float2*)(O + 8 * DHH + nt * 8) = o1;
    }
}

extern "C" void kernel_launch(void* const* d_in, const int* in_sizes, int n_in,
                              void* d_out, int out_size)
{
    const float* logits = (const float*)d_in[0];
    const float* value  = (const float*)d_in[1];
    const float* sinks  = (const float*)d_in[2];
    float* out = (float*)d_out;

    cudaFuncSetAttribute(attn_sink_kernel,
                         cudaFuncAttributeMaxDynamicSharedMemorySize, SMEM_BYTES);

    dim3 grid(SQ / BM, HH, 1);
    attn_sink_kernel<<<grid, 128, SMEM_BYTES>>>(logits, value, sinks, out);
}

// round 2
// speedup vs baseline: 1.1383x; 1.1383x over previous
#include <cuda_runtime.h>
#include <cstdint>
#include <cstddef>

#define HH   32
#define SQ   2048
#define SKK  2048
#define DHH  128
#define BM   128
#define BN   64
#define NTILES (SKK / BN)          // 32
#define VSTR 132                   // floats per V row in smem (128 + 4 pad)
#define LOG2E 1.4426950408889634f

// two V buffers of [BN][VSTR] floats
#define SMEM_BYTES (2 * BN * VSTR * 4)

__device__ __forceinline__ uint32_t f2tf32(float f) {
    uint32_t u;
    asm("cvt.rna.tf32.f32 %0, %1;" : "=r"(u) : "f"(f));
    return u;
}
__device__ __forceinline__ float ex2f(float x) {
    float y;
    asm("ex2.approx.ftz.f32 %0, %1;" : "=f"(y) : "f"(x));
    return y;
}
__device__ __forceinline__ void cp16(uint32_t dst, const float* src) {
    asm volatile("cp.async.cg.shared.global [%0], [%1], 16;\n" :: "r"(dst), "l"(src));
}

__global__ __launch_bounds__(128, 2)
void attn_sink_kernel(const float* __restrict__ logits,
                      const float* __restrict__ value,
                      const float* __restrict__ sinks,
                      float* __restrict__ out)
{
    extern __shared__ float smem[];   // [2][BN][VSTR]

    const int qt   = blockIdx.x;      // 0..15
    const int h    = blockIdx.y;      // 0..31
    const int tid  = threadIdx.x;
    const int lane = tid & 31;
    const int w    = tid >> 5;        // warp 0..3 owns rows [w*32, w*32+32)
    const int lc   = lane & 3;
    const int lr   = lane >> 2;

    const float* Lg = logits + ((size_t)h * SQ + (size_t)qt * BM) * SKK;
    const float* Vg = value  + (size_t)h * SKK * DHH;

    const uint32_t sbase = (uint32_t)__cvta_generic_to_shared(smem);

    // ---- V staging mapping: thread -> (16 rows x one float4 column) ----
    const int sc  = lane;             // float4 column 0..31
    const int sr0 = w * 16;           // rows [sr0, sr0+16)

    // prologue: stage tile 0 into buffer 0
    {
        const float* Vt = Vg;
#pragma unroll
        for (int i = 0; i < 16; ++i) {
            int r = sr0 + i;
            cp16(sbase + (uint32_t)(r * VSTR + sc * 4) * 4u, Vt + r * DHH + sc * 4);
        }
        asm volatile("cp.async.commit_group;\n");
    }

    // accumulators: [mi][nt][4]
    float acc[2][16][4];
#pragma unroll
    for (int mi = 0; mi < 2; ++mi)
#pragma unroll
        for (int nt = 0; nt < 16; ++nt) {
            acc[mi][nt][0] = 0.f; acc[mi][nt][1] = 0.f;
            acc[mi][nt][2] = 0.f; acc[mi][nt][3] = 0.f;
        }
    // per-lane partial row sums of exp(logit): [mi][row0/row0+8]
    float psum[2][2] = {{0.f, 0.f}, {0.f, 0.f}};

    for (int kt = 0; kt < NTILES; ++kt) {
        const int cur = kt & 1;

        __syncthreads();   // all reads of buf[cur^1] (prev iter) done before refill

        if (kt + 1 < NTILES) {
            const float* Vt = Vg + (size_t)(kt + 1) * BN * DHH;
            uint32_t db = sbase + (uint32_t)((cur ^ 1) * BN * VSTR) * 4u;
#pragma unroll
            for (int i = 0; i < 16; ++i) {
                int r = sr0 + i;
                cp16(db + (uint32_t)(r * VSTR + sc * 4) * 4u, Vt + r * DHH + sc * 4);
            }
            asm volatile("cp.async.commit_group;\n");
            asm volatile("cp.async.wait_group 1;\n");   // tile kt's copy complete
        } else {
            asm volatile("cp.async.wait_group 0;\n");
        }
        __syncthreads();   // buf[cur] visible to all warps

        const float* Vs = smem + cur * BN * VSTR;
        const float* Lt = Lg + kt * BN;

        // two k-halves of 4 k-subtiles each (keeps A/P register pressure low)
#pragma unroll
        for (int half = 0; half < 2; ++half) {
            // ---- A fragments straight from GMEM (k-col permutation 2c,2c+1) ----
            float2 A[2][4][2];
#pragma unroll
            for (int mi = 0; mi < 2; ++mi) {
                const int r0 = w * 32 + mi * 16 + lr;
#pragma unroll
                for (int kk = 0; kk < 4; ++kk) {
                    const int col = (half * 4 + kk) * 8 + 2 * lc;
                    A[mi][kk][0] = *(const float2*)(Lt + (size_t)r0 * SKK + col);
                    A[mi][kk][1] = *(const float2*)(Lt + (size_t)(r0 + 8) * SKK + col);
                }
            }
            // ---- exp -> tf32 probs + partial sums ----
            uint32_t P[2][4][4];
#pragma unroll
            for (int mi = 0; mi < 2; ++mi)
#pragma unroll
                for (int kk = 0; kk < 4; ++kk) {
                    float p0 = ex2f(A[mi][kk][0].x * LOG2E);
                    float p2 = ex2f(A[mi][kk][0].y * LOG2E);
                    float p1 = ex2f(A[mi][kk][1].x * LOG2E);
                    float p3 = ex2f(A[mi][kk][1].y * LOG2E);
                    psum[mi][0] += p0 + p2;
                    psum[mi][1] += p1 + p3;
                    P[mi][kk][0] = f2tf32(p0);
                    P[mi][kk][1] = f2tf32(p1);
                    P[mi][kk][2] = f2tf32(p2);
                    P[mi][kk][3] = f2tf32(p3);
                }
            // ---- P @ V : B fragments shared across both m-subtiles ----
#pragma unroll
            for (int kk = 0; kk < 4; ++kk) {
                const int k = half * 4 + kk;
                const float* vrow = Vs + (k * 8 + 2 * lc) * VSTR;   // row 2c
#pragma unroll
                for (int nt = 0; nt < 16; ++nt) {
                    uint32_t b0 = __float_as_uint(vrow[nt * 8 + lr]);          // row 2c
                    uint32_t b1 = __float_as_uint(vrow[VSTR + nt * 8 + lr]);   // row 2c+1
#pragma unroll
                    for (int mi = 0; mi < 2; ++mi) {
                        asm volatile(
                            "mma.sync.aligned.m16n8k8.row.col.f32.tf32.tf32.f32 "
                            "{%0,%1,%2,%3}, {%4,%5,%6,%7}, {%8,%9}, {%0,%1,%2,%3};\n"
                            : "+f"(acc[mi][nt][0]), "+f"(acc[mi][nt][1]),
                              "+f"(acc[mi][nt][2]), "+f"(acc[mi][nt][3])
                            : "r"(P[mi][kk][0]), "r"(P[mi][kk][1]),
                              "r"(P[mi][kk][2]), "r"(P[mi][kk][3]),
                              "r"(b0), "r"(b1));
                    }
                }
            }
        }
    }

    // ---- final row-sum reduce over the quad (cols), add sink, normalize ----
#pragma unroll
    for (int mi = 0; mi < 2; ++mi)
#pragma unroll
        for (int j = 0; j < 2; ++j) {
            psum[mi][j] += __shfl_xor_sync(0xffffffffu, psum[mi][j], 1);
            psum[mi][j] += __shfl_xor_sync(0xffffffffu, psum[mi][j], 2);
        }
    const float snk = ex2f(sinks[h] * LOG2E);
    float inv[2][2];
#pragma unroll
    for (int mi = 0; mi < 2; ++mi) {
        inv[mi][0] = 1.0f / (psum[mi][0] + snk);
        inv[mi][1] = 1.0f / (psum[mi][1] + snk);
    }

    float* Ob = out + ((size_t)h * SQ + (size_t)qt * BM) * DHH;
#pragma unroll
    for (int mi = 0; mi < 2; ++mi) {
        const int r0 = w * 32 + mi * 16 + lr;
        float* O0 = Ob + (size_t)r0 * DHH + 2 * lc;
        float* O1 = Ob + (size_t)(r0 + 8) * DHH + 2 * lc;
#pragma unroll
        for (int nt = 0; nt < 16; ++nt) {
            *(float2*)(O0 + nt * 8) =
                make_float2(acc[mi][nt][0] * inv[mi][0], acc[mi][nt][1] * inv[mi][0]);
            *(float2*)(O1 + nt * 8) =
                make_float2(acc[mi][nt][2] * inv[mi][1], acc[mi][nt][3] * inv[mi][1]);
        }
    }
}

extern "C" void kernel_launch(void* const* d_in, const int* in_sizes, int n_in,
                              void* d_out, int out_size)
{
    const float* logits = (const float*)d_in[0];
    const float* value  = (const float*)d_in[1];
    const float* sinks  = (const float*)d_in[2];
    float* out = (float*)d_out;

    cudaFuncSetAttribute(attn_sink_kernel,
                         cudaFuncAttributeMaxDynamicSharedMemorySize, SMEM_BYTES);

    dim3 grid(SQ / BM, HH, 1);
    attn_sink_kernel<<<grid, 128, SMEM_BYTES>>>(logits, value, sinks, out);
}